// round 13
// baseline (speedup 1.0000x reference)
#include <cuda_runtime.h>
#include <cstdint>
#include <math_constants.h>

// Problem constants (fixed by the dataset)
#define N_PTS   98304      // B*H*W = 96*32*32
#define C_DIM   256
#define HW      1024       // 32*32
#define NSAMP   491
#define NITER   490        // NSAMP - 1
#define NBLK    128        // persistent blocks (98304/768), 1/SM (smem-forced)
#define NTHR    768        // 24 warps/block; each warp owns 32 points
#define TILE_U2 (NTHR * 32)          // uint2 per block tile (24576 = 192KB)

// Scratch (device globals: no allocation allowed)
__device__ float  g_feat[(size_t)N_PTS * C_DIM];  // [N][C] fp32 exact, ~100.6 MB
__device__ uint2  g_q8[(size_t)N_PTS * 32];       // [N][32] packed int8 rows, 25.2 MB
__device__ float4 g_qmeta[N_PTS];                 // (scale, nvh2, env, 0) per point
__device__ unsigned long long g_bmax[2][NBLK];    // double-buffered block maxima
__device__ int g_sel[NSAMP];                      // selected indices
__device__ volatile unsigned g_bar;               // grid barrier counter

// ---------------------------------------------------------------------------
// Init A: reset barrier + tiled transpose [B,C,HW] -> g_feat[(b*HW+hw)*C + c]
// ---------------------------------------------------------------------------
__global__ void k_init(const float* __restrict__ in) {
    if (blockIdx.x == 0 && threadIdx.x == 0) { g_bar = 0; g_sel[0] = 0; }
    __shared__ float tile[32][33];
    const int b  = blockIdx.x >> 8;
    const int t  = blockIdx.x & 255;
    const int ct = t >> 5;            // c-tile 0..7
    const int ht = t & 31;            // hw-tile 0..31
    const int tx = threadIdx.x & 31;
    const int ty = threadIdx.x >> 5;  // 0..7

    const float* src = in + ((size_t)b * C_DIM + ct * 32) * HW + ht * 32;
    #pragma unroll
    for (int r = 0; r < 4; ++r)
        tile[ty + r * 8][tx] = src[(size_t)(ty + r * 8) * HW + tx];
    __syncthreads();

    float* dst = g_feat + ((size_t)b * HW + ht * 32) * C_DIM + ct * 32;
    #pragma unroll
    for (int r = 0; r < 4; ++r)
        dst[(size_t)(ty + r * 8) * C_DIM + tx] = tile[tx][ty + r * 8];
}

// ---------------------------------------------------------------------------
// Init B: int8 quantization. One warp per point; lane l owns cols 8l..8l+7.
// ---------------------------------------------------------------------------
__global__ void k_quant() {
    const int p    = blockIdx.x * 8 + (threadIdx.x >> 5);
    const int lane = threadIdx.x & 31;
    const float4* row = reinterpret_cast<const float4*>(g_feat + (size_t)p * C_DIM);
    float4 va = row[2 * lane];
    float4 vb = row[2 * lane + 1];

    float m = fmaxf(fmaxf(fmaxf(fabsf(va.x), fabsf(va.y)), fmaxf(fabsf(va.z), fabsf(va.w))),
                    fmaxf(fmaxf(fabsf(vb.x), fabsf(vb.y)), fmaxf(fabsf(vb.z), fabsf(vb.w))));
    #pragma unroll
    for (int off = 16; off; off >>= 1)
        m = fmaxf(m, __shfl_xor_sync(0xffffffffu, m, off));
    m = fmaxf(m, 1e-30f);
    const float scale = m * (1.f / 127.f);
    const float inv   = 127.f / m;

    int i0 = (int)rintf(va.x * inv), i1 = (int)rintf(va.y * inv);
    int i2 = (int)rintf(va.z * inv), i3 = (int)rintf(va.w * inv);
    int i4 = (int)rintf(vb.x * inv), i5 = (int)rintf(vb.y * inv);
    int i6 = (int)rintf(vb.z * inv), i7 = (int)rintf(vb.w * inv);

    unsigned w0 = (unsigned)(i0 & 0xff) | ((unsigned)(i1 & 0xff) << 8)
                | ((unsigned)(i2 & 0xff) << 16) | ((unsigned)(i3 & 0xff) << 24);
    unsigned w1 = (unsigned)(i4 & 0xff) | ((unsigned)(i5 & 0xff) << 8)
                | ((unsigned)(i6 & 0xff) << 16) | ((unsigned)(i7 & 0xff) << 24);
    g_q8[(size_t)p * 32 + lane] = make_uint2(w0, w1);

    int s2 = __dp4a((int)w0, (int)w0, __dp4a((int)w1, (int)w1, 0));
    float e, se2 = 0.f;
    e = va.x - scale * (float)i0; se2 = fmaf(e, e, se2);
    e = va.y - scale * (float)i1; se2 = fmaf(e, e, se2);
    e = va.z - scale * (float)i2; se2 = fmaf(e, e, se2);
    e = va.w - scale * (float)i3; se2 = fmaf(e, e, se2);
    e = vb.x - scale * (float)i4; se2 = fmaf(e, e, se2);
    e = vb.y - scale * (float)i5; se2 = fmaf(e, e, se2);
    e = vb.z - scale * (float)i6; se2 = fmaf(e, e, se2);
    e = vb.w - scale * (float)i7; se2 = fmaf(e, e, se2);
    #pragma unroll
    for (int off = 16; off; off >>= 1) {
        s2  += __shfl_xor_sync(0xffffffffu, s2, off);
        se2 += __shfl_xor_sync(0xffffffffu, se2, off);
    }
    if (lane == 0)
        g_qmeta[p] = make_float4(scale,
                                 scale * scale * (float)s2,
                                 sqrtf(se2 * 1.0001f + 1e-12f) * 1.0001f,
                                 0.f);
}

// ---------------------------------------------------------------------------
// Persistent FPS: SMEM int8 screen, precomputed query quant, register query,
// fused (publish+spin+reduce) barrier -> only 2 __syncthreads per iteration.
// Exact path (on screen failure) is the verified bit-exact XLA warp reduce.
// ---------------------------------------------------------------------------
extern __shared__ uint2 s_tile[];               // [768 pts][32 uint2] = 192 KB

__global__ void __launch_bounds__(NTHR, 1) k_fps() {
    __shared__ unsigned long long swarp[NTHR / 32];
    __shared__ int s_qidx;

    const int tid  = threadIdx.x;
    const int lane = tid & 31;
    const int wid  = tid >> 5;                  // 0..23
    const int n0   = blockIdx.x * NTHR + wid * 32;
    const float* __restrict__ fbase = g_feat + (size_t)n0 * C_DIM;
    const int mypoint = n0 + lane;

    // ---- stage this block's int8 tile into shared memory (once) ----
    {
        const uint2* __restrict__ gsrc = g_q8 + (size_t)blockIdx.x * NTHR * 32;
        #pragma unroll
        for (int i = 0; i < TILE_U2 / NTHR; ++i)      // 32 iterations
            s_tile[i * NTHR + tid] = gsrc[i * NTHR + tid];
    }
    const uint2* __restrict__ qbase = s_tile + wid * 32 * 32;

    float mind = CUDART_INF_F;

    // hoisted per-point screen constants
    const float4 qm_self = g_qmeta[mypoint];
    const float mysv   = qm_self.x;
    const float mynvh2 = qm_self.y;
    const float myenv  = qm_self.z;

    // initial query: index 0 (all query state in registers)
    uint2  qrow = g_q8[lane];
    float4 qm   = g_qmeta[0];
    float  qv[8];
    #pragma unroll
    for (int j = 0; j < 8; ++j) qv[j] = g_feat[j * 32 + lane];
    __syncthreads();                            // s_tile ready

    for (int it = 0; it < NITER; ++it) {
        const int q0 = (int)qrow.x;
        const int q1 = (int)qrow.y;
        const float ss    = mysv * qm.x;
        const float cnqh2 = qm.y;
        const float cenq  = qm.z;

        // ---- int8 screen from SMEM: exact integer dots, 32 points/warp ----
        int p16[16];
        #pragma unroll
        for (int i = 0; i < 16; ++i) {
            uint2 a = qbase[i * 32 + lane];
            uint2 b = qbase[(i + 16) * 32 + lane];
            int da = __dp4a((int)a.y, q1, __dp4a((int)a.x, q0, 0));
            int db = __dp4a((int)b.y, q1, __dp4a((int)b.x, q0, 0));
            int send = (lane & 16) ? da : db;
            int keep = (lane & 16) ? db : da;
            p16[i] = keep + __shfl_xor_sync(0xffffffffu, send, 16);
        }
        #pragma unroll
        for (int off = 8; off >= 1; off >>= 1) {
            #pragma unroll
            for (int k = 0; k < 8; ++k) {
                if (k < off) {
                    int send = (lane & off) ? p16[k] : p16[k + off];
                    int keep = (lane & off) ? p16[k + off] : p16[k];
                    p16[k] = keep + __shfl_xor_sync(0xffffffffu, send, off);
                }
            }
        }
        // certified lower bound: d >= ||vhat-qhat|| - ||ev|| - ||eq|| - pad
        float t  = mynvh2 + cnqh2 - 2.f * ss * (float)p16[0];
        float lb = sqrtf(fmaxf(t, 0.f)) * (1.f - 1e-6f) - myenv - cenq - 0.01f;
        bool need = !(lb >= mind);                 // NaN/inf-safe

        // ---- exact recheck (bit-exact XLA reduce) for flagged points.
        //      Lane l needs q[j*32+l] == qv[j] (identical fp32 words). ----
        unsigned mask = __ballot_sync(0xffffffffu, need);
        while (mask) {
            const int i = __ffs(mask) - 1;
            mask &= mask - 1;
            const float* row = fbase + (size_t)i * C_DIM;
            float a = 0.f;
            #pragma unroll
            for (int j = 0; j < 8; ++j) {
                float v = row[j * 32 + lane];
                float d = __fsub_rn(v, qv[j]);
                a = __fadd_rn(a, __fmul_rn(d, d));     // no contraction
            }
            #pragma unroll
            for (int off = 16; off; off >>= 1)
                a = __fadd_rn(a, __shfl_down_sync(0xffffffffu, a, off));
            float s = __shfl_sync(0xffffffffu, a, 0);
            if (lane == i) mind = fminf(mind, __fsqrt_rn(s));
        }

        // ---- argmax, first-index-wins: key = bits(min_d)<<32 | ~idx ----
        unsigned long long best =
            ((unsigned long long)__float_as_uint(mind) << 32) | (unsigned)~mypoint;
        #pragma unroll
        for (int off = 16; off; off >>= 1) {
            unsigned long long o = __shfl_xor_sync(0xffffffffu, best, off);
            if (o > best) best = o;
        }
        if (lane == 0) swarp[wid] = best;
        __syncthreads();                                   // sync A

        // ---- fused barrier: publish + counter + spin + slot reduce (wid 0) ----
        if (wid == 0) {
            unsigned long long b = (lane < NTHR / 32) ? swarp[lane] : 0ULL;
            #pragma unroll
            for (int off = 16; off; off >>= 1) {
                unsigned long long o = __shfl_xor_sync(0xffffffffu, b, off);
                if (o > b) b = o;
            }
            if (lane == 0) {
                *(volatile unsigned long long*)&g_bmax[it & 1][blockIdx.x] = b;
                __threadfence();                           // release
                atomicAdd((unsigned*)&g_bar, 1u);
                const unsigned target = (unsigned)NBLK * (unsigned)(it + 1);
                while (g_bar < target) { }                 // grid barrier spin
                __threadfence();                           // acquire
            }
            __syncwarp();                                  // lanes wait for spin
            unsigned long long g = 0;
            #pragma unroll
            for (int j = 0; j < NBLK / 32; ++j) {
                unsigned long long o =
                    *(volatile unsigned long long*)&g_bmax[it & 1][j * 32 + lane];
                if (o > g) g = o;
            }
            #pragma unroll
            for (int off = 16; off; off >>= 1) {
                unsigned long long o = __shfl_xor_sync(0xffffffffu, g, off);
                if (o > g) g = o;
            }
            if (lane == 0) {
                const int q = (int)~(unsigned)g;
                s_qidx = q;
                if (blockIdx.x == 0) g_sel[it + 1] = q;
            }
        }
        __syncthreads();                                   // sync B

        // ---- next-query loads straight into registers ----
        const int q = s_qidx;
        qrow = g_q8[(size_t)q * 32 + lane];
        qm   = g_qmeta[q];
        const float* qr = g_feat + (size_t)q * C_DIM;
        #pragma unroll
        for (int j = 0; j < 8; ++j) qv[j] = qr[j * 32 + lane];
    }
}

// ---------------------------------------------------------------------------
// Gather: out = [sampled feats (491*256) | sampled weights (491) | indices (491)]
// ---------------------------------------------------------------------------
__global__ void k_gather(const float* __restrict__ w, float* __restrict__ out) {
    const int s = blockIdx.x;           // 0..490
    const int idx = g_sel[s];
    out[s * C_DIM + threadIdx.x] = g_feat[(size_t)idx * C_DIM + threadIdx.x];
    if (threadIdx.x == 0) {
        out[NSAMP * C_DIM + s]         = w[idx];
        out[NSAMP * C_DIM + NSAMP + s] = (float)idx;
    }
}

// ---------------------------------------------------------------------------
extern "C" void kernel_launch(void* const* d_in, const int* in_sizes, int n_in,
                              void* d_out, int out_size) {
    const float* features = (const float*)d_in[0];   // [96,256,32,32] f32
    const float* weights  = (const float*)d_in[1];   // [98304] f32
    (void)in_sizes; (void)n_in; (void)out_size;      // num_samples fixed at 491

    const size_t dyn_smem = (size_t)TILE_U2 * sizeof(uint2);   // 192 KB
    static bool attr_set = false;
    if (!attr_set) {
        cudaFuncSetAttribute(k_fps, cudaFuncAttributeMaxDynamicSharedMemorySize,
                             (int)dyn_smem);
        attr_set = true;
    }

    k_init<<<(96 * 256), 256>>>(features);
    k_quant<<<N_PTS / 8, 256>>>();
    k_fps<<<NBLK, NTHR, dyn_smem>>>();
    k_gather<<<NSAMP, C_DIM>>>(weights, (float*)d_out);
}

// round 14
// speedup vs baseline: 1.0013x; 1.0013x over previous
#include <cuda_runtime.h>
#include <cstdint>
#include <math_constants.h>

// Problem constants (fixed by the dataset)
#define N_PTS   98304      // B*H*W = 96*32*32
#define C_DIM   256
#define HW      1024       // 32*32
#define NSAMP   491
#define NITER   490        // NSAMP - 1
#define NBLK    128        // persistent blocks (98304/768), 1/SM (smem-forced)
#define NTHR    768        // 24 warps/block; each warp owns 32 points
#define TILE_U2 (NTHR * 32)          // uint2 per block tile (24576 = 192KB)

// Scratch (device globals: no allocation allowed)
__device__ float  g_feat[(size_t)N_PTS * C_DIM];  // [N][C] fp32 exact, ~100.6 MB
__device__ uint2  g_q8[(size_t)N_PTS * 32];       // [N][32] packed int8 rows, 25.2 MB
__device__ float4 g_qmeta[N_PTS];                 // (scale, nvh2, env, 0) per point
__device__ unsigned long long g_bmax[2][NBLK];    // double-buffered block maxima
__device__ int g_sel[NSAMP];                      // selected indices
__device__ volatile unsigned g_bar;               // grid barrier counter

// ---------------------------------------------------------------------------
// Init A: reset barrier + tiled transpose [B,C,HW] -> g_feat[(b*HW+hw)*C + c]
// ---------------------------------------------------------------------------
__global__ void k_init(const float* __restrict__ in) {
    if (blockIdx.x == 0 && threadIdx.x == 0) { g_bar = 0; g_sel[0] = 0; }
    __shared__ float tile[32][33];
    const int b  = blockIdx.x >> 8;
    const int t  = blockIdx.x & 255;
    const int ct = t >> 5;            // c-tile 0..7
    const int ht = t & 31;            // hw-tile 0..31
    const int tx = threadIdx.x & 31;
    const int ty = threadIdx.x >> 5;  // 0..7

    const float* src = in + ((size_t)b * C_DIM + ct * 32) * HW + ht * 32;
    #pragma unroll
    for (int r = 0; r < 4; ++r)
        tile[ty + r * 8][tx] = src[(size_t)(ty + r * 8) * HW + tx];
    __syncthreads();

    float* dst = g_feat + ((size_t)b * HW + ht * 32) * C_DIM + ct * 32;
    #pragma unroll
    for (int r = 0; r < 4; ++r)
        dst[(size_t)(ty + r * 8) * C_DIM + tx] = tile[tx][ty + r * 8];
}

// ---------------------------------------------------------------------------
// Init B: int8 quantization. One warp per point; lane l owns cols 8l..8l+7.
// ---------------------------------------------------------------------------
__global__ void k_quant() {
    const int p    = blockIdx.x * 8 + (threadIdx.x >> 5);
    const int lane = threadIdx.x & 31;
    const float4* row = reinterpret_cast<const float4*>(g_feat + (size_t)p * C_DIM);
    float4 va = row[2 * lane];
    float4 vb = row[2 * lane + 1];

    float m = fmaxf(fmaxf(fmaxf(fabsf(va.x), fabsf(va.y)), fmaxf(fabsf(va.z), fabsf(va.w))),
                    fmaxf(fmaxf(fabsf(vb.x), fabsf(vb.y)), fmaxf(fabsf(vb.z), fabsf(vb.w))));
    #pragma unroll
    for (int off = 16; off; off >>= 1)
        m = fmaxf(m, __shfl_xor_sync(0xffffffffu, m, off));
    m = fmaxf(m, 1e-30f);
    const float scale = m * (1.f / 127.f);
    const float inv   = 127.f / m;

    int i0 = (int)rintf(va.x * inv), i1 = (int)rintf(va.y * inv);
    int i2 = (int)rintf(va.z * inv), i3 = (int)rintf(va.w * inv);
    int i4 = (int)rintf(vb.x * inv), i5 = (int)rintf(vb.y * inv);
    int i6 = (int)rintf(vb.z * inv), i7 = (int)rintf(vb.w * inv);

    unsigned w0 = (unsigned)(i0 & 0xff) | ((unsigned)(i1 & 0xff) << 8)
                | ((unsigned)(i2 & 0xff) << 16) | ((unsigned)(i3 & 0xff) << 24);
    unsigned w1 = (unsigned)(i4 & 0xff) | ((unsigned)(i5 & 0xff) << 8)
                | ((unsigned)(i6 & 0xff) << 16) | ((unsigned)(i7 & 0xff) << 24);
    g_q8[(size_t)p * 32 + lane] = make_uint2(w0, w1);

    int s2 = __dp4a((int)w0, (int)w0, __dp4a((int)w1, (int)w1, 0));
    float e, se2 = 0.f;
    e = va.x - scale * (float)i0; se2 = fmaf(e, e, se2);
    e = va.y - scale * (float)i1; se2 = fmaf(e, e, se2);
    e = va.z - scale * (float)i2; se2 = fmaf(e, e, se2);
    e = va.w - scale * (float)i3; se2 = fmaf(e, e, se2);
    e = vb.x - scale * (float)i4; se2 = fmaf(e, e, se2);
    e = vb.y - scale * (float)i5; se2 = fmaf(e, e, se2);
    e = vb.z - scale * (float)i6; se2 = fmaf(e, e, se2);
    e = vb.w - scale * (float)i7; se2 = fmaf(e, e, se2);
    #pragma unroll
    for (int off = 16; off; off >>= 1) {
        s2  += __shfl_xor_sync(0xffffffffu, s2, off);
        se2 += __shfl_xor_sync(0xffffffffu, se2, off);
    }
    if (lane == 0)
        g_qmeta[p] = make_float4(scale,
                                 scale * scale * (float)s2,
                                 sqrtf(se2 * 1.0001f + 1e-12f) * 1.0001f,
                                 0.f);
}

// ---------------------------------------------------------------------------
// Persistent FPS: SMEM int8 screen, precomputed query quant, register query,
// fused (publish+spin+reduce) barrier -> only 2 __syncthreads per iteration.
// Exact path (on screen failure) is the verified bit-exact XLA warp reduce.
// ---------------------------------------------------------------------------
extern __shared__ uint2 s_tile[];               // [768 pts][32 uint2] = 192 KB

__global__ void __launch_bounds__(NTHR, 1) k_fps() {
    __shared__ unsigned long long swarp[NTHR / 32];
    __shared__ int s_qidx;

    const int tid  = threadIdx.x;
    const int lane = tid & 31;
    const int wid  = tid >> 5;                  // 0..23
    const int n0   = blockIdx.x * NTHR + wid * 32;
    const float* __restrict__ fbase = g_feat + (size_t)n0 * C_DIM;
    const int mypoint = n0 + lane;

    // ---- stage this block's int8 tile into shared memory (once) ----
    {
        const uint2* __restrict__ gsrc = g_q8 + (size_t)blockIdx.x * NTHR * 32;
        #pragma unroll
        for (int i = 0; i < TILE_U2 / NTHR; ++i)      // 32 iterations
            s_tile[i * NTHR + tid] = gsrc[i * NTHR + tid];
    }
    const uint2* __restrict__ qbase = s_tile + wid * 32 * 32;

    float mind = CUDART_INF_F;

    // hoisted per-point screen constants
    const float4 qm_self = g_qmeta[mypoint];
    const float mysv   = qm_self.x;
    const float mynvh2 = qm_self.y;
    const float myenv  = qm_self.z;

    // initial query: index 0 (all query state in registers)
    uint2  qrow = g_q8[lane];
    float4 qm   = g_qmeta[0];
    float  qv[8];
    #pragma unroll
    for (int j = 0; j < 8; ++j) qv[j] = g_feat[j * 32 + lane];
    __syncthreads();                            // s_tile ready

    for (int it = 0; it < NITER; ++it) {
        const int q0 = (int)qrow.x;
        const int q1 = (int)qrow.y;
        const float ss    = mysv * qm.x;
        const float cnqh2 = qm.y;
        const float cenq  = qm.z;

        // ---- int8 screen from SMEM: exact integer dots, 32 points/warp ----
        int p16[16];
        #pragma unroll
        for (int i = 0; i < 16; ++i) {
            uint2 a = qbase[i * 32 + lane];
            uint2 b = qbase[(i + 16) * 32 + lane];
            int da = __dp4a((int)a.y, q1, __dp4a((int)a.x, q0, 0));
            int db = __dp4a((int)b.y, q1, __dp4a((int)b.x, q0, 0));
            int send = (lane & 16) ? da : db;
            int keep = (lane & 16) ? db : da;
            p16[i] = keep + __shfl_xor_sync(0xffffffffu, send, 16);
        }
        #pragma unroll
        for (int off = 8; off >= 1; off >>= 1) {
            #pragma unroll
            for (int k = 0; k < 8; ++k) {
                if (k < off) {
                    int send = (lane & off) ? p16[k] : p16[k + off];
                    int keep = (lane & off) ? p16[k + off] : p16[k];
                    p16[k] = keep + __shfl_xor_sync(0xffffffffu, send, off);
                }
            }
        }
        // certified lower bound: d >= ||vhat-qhat|| - ||ev|| - ||eq|| - pad
        float t  = mynvh2 + cnqh2 - 2.f * ss * (float)p16[0];
        float lb = sqrtf(fmaxf(t, 0.f)) * (1.f - 1e-6f) - myenv - cenq - 0.01f;
        bool need = !(lb >= mind);                 // NaN/inf-safe

        // ---- exact recheck (bit-exact XLA reduce) for flagged points.
        //      Lane l needs q[j*32+l] == qv[j] (identical fp32 words). ----
        unsigned mask = __ballot_sync(0xffffffffu, need);
        while (mask) {
            const int i = __ffs(mask) - 1;
            mask &= mask - 1;
            const float* row = fbase + (size_t)i * C_DIM;
            float a = 0.f;
            #pragma unroll
            for (int j = 0; j < 8; ++j) {
                float v = row[j * 32 + lane];
                float d = __fsub_rn(v, qv[j]);
                a = __fadd_rn(a, __fmul_rn(d, d));     // no contraction
            }
            #pragma unroll
            for (int off = 16; off; off >>= 1)
                a = __fadd_rn(a, __shfl_down_sync(0xffffffffu, a, off));
            float s = __shfl_sync(0xffffffffu, a, 0);
            if (lane == i) mind = fminf(mind, __fsqrt_rn(s));
        }

        // ---- argmax, first-index-wins: key = bits(min_d)<<32 | ~idx ----
        unsigned long long best =
            ((unsigned long long)__float_as_uint(mind) << 32) | (unsigned)~mypoint;
        #pragma unroll
        for (int off = 16; off; off >>= 1) {
            unsigned long long o = __shfl_xor_sync(0xffffffffu, best, off);
            if (o > best) best = o;
        }
        if (lane == 0) swarp[wid] = best;
        __syncthreads();                                   // sync A

        // ---- fused barrier: publish + counter + spin + slot reduce (wid 0) ----
        if (wid == 0) {
            unsigned long long b = (lane < NTHR / 32) ? swarp[lane] : 0ULL;
            #pragma unroll
            for (int off = 16; off; off >>= 1) {
                unsigned long long o = __shfl_xor_sync(0xffffffffu, b, off);
                if (o > b) b = o;
            }
            if (lane == 0) {
                *(volatile unsigned long long*)&g_bmax[it & 1][blockIdx.x] = b;
                __threadfence();                           // release
                atomicAdd((unsigned*)&g_bar, 1u);
                const unsigned target = (unsigned)NBLK * (unsigned)(it + 1);
                while (g_bar < target) { }                 // grid barrier spin
                __threadfence();                           // acquire
            }
            __syncwarp();                                  // lanes wait for spin
            unsigned long long g = 0;
            #pragma unroll
            for (int j = 0; j < NBLK / 32; ++j) {
                unsigned long long o =
                    *(volatile unsigned long long*)&g_bmax[it & 1][j * 32 + lane];
                if (o > g) g = o;
            }
            #pragma unroll
            for (int off = 16; off; off >>= 1) {
                unsigned long long o = __shfl_xor_sync(0xffffffffu, g, off);
                if (o > g) g = o;
            }
            if (lane == 0) {
                const int q = (int)~(unsigned)g;
                s_qidx = q;
                if (blockIdx.x == 0) g_sel[it + 1] = q;
            }
        }
        __syncthreads();                                   // sync B

        // ---- next-query loads straight into registers ----
        const int q = s_qidx;
        qrow = g_q8[(size_t)q * 32 + lane];
        qm   = g_qmeta[q];
        const float* qr = g_feat + (size_t)q * C_DIM;
        #pragma unroll
        for (int j = 0; j < 8; ++j) qv[j] = qr[j * 32 + lane];
    }
}

// ---------------------------------------------------------------------------
// Gather: out = [sampled feats (491*256) | sampled weights (491) | indices (491)]
// ---------------------------------------------------------------------------
__global__ void k_gather(const float* __restrict__ w, float* __restrict__ out) {
    const int s = blockIdx.x;           // 0..490
    const int idx = g_sel[s];
    out[s * C_DIM + threadIdx.x] = g_feat[(size_t)idx * C_DIM + threadIdx.x];
    if (threadIdx.x == 0) {
        out[NSAMP * C_DIM + s]         = w[idx];
        out[NSAMP * C_DIM + NSAMP + s] = (float)idx;
    }
}

// ---------------------------------------------------------------------------
extern "C" void kernel_launch(void* const* d_in, const int* in_sizes, int n_in,
                              void* d_out, int out_size) {
    const float* features = (const float*)d_in[0];   // [96,256,32,32] f32
    const float* weights  = (const float*)d_in[1];   // [98304] f32
    (void)in_sizes; (void)n_in; (void)out_size;      // num_samples fixed at 491

    const size_t dyn_smem = (size_t)TILE_U2 * sizeof(uint2);   // 192 KB
    static bool attr_set = false;
    if (!attr_set) {
        cudaFuncSetAttribute(k_fps, cudaFuncAttributeMaxDynamicSharedMemorySize,
                             (int)dyn_smem);
        attr_set = true;
    }

    k_init<<<(96 * 256), 256>>>(features);
    k_quant<<<N_PTS / 8, 256>>>();
    k_fps<<<NBLK, NTHR, dyn_smem>>>();
    k_gather<<<NSAMP, C_DIM>>>(weights, (float*)d_out);
}

// round 15
// speedup vs baseline: 1.0241x; 1.0228x over previous
#include <cuda_runtime.h>
#include <cstdint>
#include <math_constants.h>

// Problem constants (fixed by the dataset)
#define N_PTS   98304      // B*H*W = 96*32*32
#define C_DIM   256
#define HW      1024       // 32*32
#define NSAMP   491
#define NITER   490        // NSAMP - 1
#define NBLK    128        // persistent blocks (98304/768), 1/SM (smem-forced)
#define NTHR    768        // 24 warps/block; each warp owns 32 points
#define NWARP   (NTHR / 32)
#define TILE_U2 (NTHR * 32)          // uint2 per block tile (24576 = 192KB)

#define IDXMASK 0x1FFFFu   // 17 bits (N_PTS < 2^17)

// Scratch (device globals: no allocation allowed)
__device__ float  g_feat[(size_t)N_PTS * C_DIM];  // [N][C] fp32 exact, ~100.6 MB
__device__ uint2  g_q8[(size_t)N_PTS * 32];       // [N][32] packed int8 rows, 25.2 MB
__device__ float4 g_qmeta[N_PTS];                 // (scale, nvh2, env, 0) per point
__device__ unsigned long long g_key[2];           // tagged global max (parity)
__device__ int g_sel[NSAMP];                      // selected indices
__device__ volatile unsigned g_bar;               // grid barrier counter

// ---------------------------------------------------------------------------
// Init A: reset barrier + tiled transpose [B,C,HW] -> g_feat[(b*HW+hw)*C + c]
// ---------------------------------------------------------------------------
__global__ void k_init(const float* __restrict__ in) {
    if (blockIdx.x == 0 && threadIdx.x == 0) {
        g_bar = 0; g_sel[0] = 0; g_key[0] = 0ULL; g_key[1] = 0ULL;
    }
    __shared__ float tile[32][33];
    const int b  = blockIdx.x >> 8;
    const int t  = blockIdx.x & 255;
    const int ct = t >> 5;            // c-tile 0..7
    const int ht = t & 31;            // hw-tile 0..31
    const int tx = threadIdx.x & 31;
    const int ty = threadIdx.x >> 5;  // 0..7

    const float* src = in + ((size_t)b * C_DIM + ct * 32) * HW + ht * 32;
    #pragma unroll
    for (int r = 0; r < 4; ++r)
        tile[ty + r * 8][tx] = src[(size_t)(ty + r * 8) * HW + tx];
    __syncthreads();

    float* dst = g_feat + ((size_t)b * HW + ht * 32) * C_DIM + ct * 32;
    #pragma unroll
    for (int r = 0; r < 4; ++r)
        dst[(size_t)(ty + r * 8) * C_DIM + tx] = tile[tx][ty + r * 8];
}

// ---------------------------------------------------------------------------
// Init B: int8 quantization. One warp per point; lane l owns cols 8l..8l+7.
// ---------------------------------------------------------------------------
__global__ void k_quant() {
    const int p    = blockIdx.x * 8 + (threadIdx.x >> 5);
    const int lane = threadIdx.x & 31;
    const float4* row = reinterpret_cast<const float4*>(g_feat + (size_t)p * C_DIM);
    float4 va = row[2 * lane];
    float4 vb = row[2 * lane + 1];

    float m = fmaxf(fmaxf(fmaxf(fabsf(va.x), fabsf(va.y)), fmaxf(fabsf(va.z), fabsf(va.w))),
                    fmaxf(fmaxf(fabsf(vb.x), fabsf(vb.y)), fmaxf(fabsf(vb.z), fabsf(vb.w))));
    #pragma unroll
    for (int off = 16; off; off >>= 1)
        m = fmaxf(m, __shfl_xor_sync(0xffffffffu, m, off));
    m = fmaxf(m, 1e-30f);
    const float scale = m * (1.f / 127.f);
    const float inv   = 127.f / m;

    int i0 = (int)rintf(va.x * inv), i1 = (int)rintf(va.y * inv);
    int i2 = (int)rintf(va.z * inv), i3 = (int)rintf(va.w * inv);
    int i4 = (int)rintf(vb.x * inv), i5 = (int)rintf(vb.y * inv);
    int i6 = (int)rintf(vb.z * inv), i7 = (int)rintf(vb.w * inv);

    unsigned w0 = (unsigned)(i0 & 0xff) | ((unsigned)(i1 & 0xff) << 8)
                | ((unsigned)(i2 & 0xff) << 16) | ((unsigned)(i3 & 0xff) << 24);
    unsigned w1 = (unsigned)(i4 & 0xff) | ((unsigned)(i5 & 0xff) << 8)
                | ((unsigned)(i6 & 0xff) << 16) | ((unsigned)(i7 & 0xff) << 24);
    g_q8[(size_t)p * 32 + lane] = make_uint2(w0, w1);

    int s2 = __dp4a((int)w0, (int)w0, __dp4a((int)w1, (int)w1, 0));
    float e, se2 = 0.f;
    e = va.x - scale * (float)i0; se2 = fmaf(e, e, se2);
    e = va.y - scale * (float)i1; se2 = fmaf(e, e, se2);
    e = va.z - scale * (float)i2; se2 = fmaf(e, e, se2);
    e = va.w - scale * (float)i3; se2 = fmaf(e, e, se2);
    e = vb.x - scale * (float)i4; se2 = fmaf(e, e, se2);
    e = vb.y - scale * (float)i5; se2 = fmaf(e, e, se2);
    e = vb.z - scale * (float)i6; se2 = fmaf(e, e, se2);
    e = vb.w - scale * (float)i7; se2 = fmaf(e, e, se2);
    #pragma unroll
    for (int off = 16; off; off >>= 1) {
        s2  += __shfl_xor_sync(0xffffffffu, s2, off);
        se2 += __shfl_xor_sync(0xffffffffu, se2, off);
    }
    if (lane == 0)
        g_qmeta[p] = make_float4(scale,
                                 scale * scale * (float)s2,
                                 sqrtf(se2 * 1.0001f + 1e-12f) * 1.0001f,
                                 0.f);
}

// ---------------------------------------------------------------------------
// Persistent FPS: SMEM int8 screen, block-cooperative exact rechecks,
// atomicMax single-word barrier with the proven counter spin.
// Exact path is the verified bit-exact XLA warp reduce (same operand pairs).
// ---------------------------------------------------------------------------
extern __shared__ uint2 s_tile[];               // [768 pts][32 uint2] = 192 KB

__global__ void __launch_bounds__(NTHR, 1) k_fps() {
    __shared__ unsigned long long swarp[NWARP];
    __shared__ int s_qidx;
    __shared__ int s_cnt;
    __shared__ short s_qpt[NTHR];               // queued local point ids
    __shared__ float s_res[NTHR];               // exact distances for queued pts

    const int tid  = threadIdx.x;
    const int lane = tid & 31;
    const int wid  = tid >> 5;                  // 0..23
    const int n0   = blockIdx.x * NTHR + wid * 32;
    const size_t blockbase = (size_t)blockIdx.x * NTHR;
    const int mypoint = n0 + lane;
    const int myloc   = wid * 32 + lane;        // local point id 0..767

    // ---- stage this block's int8 tile into shared memory (once) ----
    {
        const uint2* __restrict__ gsrc = g_q8 + blockbase * 32;
        #pragma unroll
        for (int i = 0; i < TILE_U2 / NTHR; ++i)      // 32 iterations
            s_tile[i * NTHR + tid] = gsrc[i * NTHR + tid];
    }
    const uint2* __restrict__ qbase = s_tile + wid * 32 * 32;

    float mind = CUDART_INF_F;

    // hoisted per-point screen constants
    const float4 qm_self = g_qmeta[mypoint];
    const float mysv   = qm_self.x;
    const float mynvh2 = qm_self.y;
    const float myenv  = qm_self.z;

    // initial query: index 0 (all query state in registers)
    uint2  qrow = g_q8[lane];
    float4 qm   = g_qmeta[0];
    float  qv[8];
    #pragma unroll
    for (int j = 0; j < 8; ++j) qv[j] = g_feat[j * 32 + lane];
    if (tid == 0) s_cnt = 0;
    __syncthreads();                            // s_tile + s_cnt ready

    for (int it = 0; it < NITER; ++it) {
        const int q0 = (int)qrow.x;
        const int q1 = (int)qrow.y;
        const float ss    = mysv * qm.x;
        const float cnqh2 = qm.y;
        const float cenq  = qm.z;

        // ---- int8 screen from SMEM: exact integer dots, 32 points/warp ----
        int p16[16];
        #pragma unroll
        for (int i = 0; i < 16; ++i) {
            uint2 a = qbase[i * 32 + lane];
            uint2 b = qbase[(i + 16) * 32 + lane];
            int da = __dp4a((int)a.y, q1, __dp4a((int)a.x, q0, 0));
            int db = __dp4a((int)b.y, q1, __dp4a((int)b.x, q0, 0));
            int send = (lane & 16) ? da : db;
            int keep = (lane & 16) ? db : da;
            p16[i] = keep + __shfl_xor_sync(0xffffffffu, send, 16);
        }
        #pragma unroll
        for (int off = 8; off >= 1; off >>= 1) {
            #pragma unroll
            for (int k = 0; k < 8; ++k) {
                if (k < off) {
                    int send = (lane & off) ? p16[k] : p16[k + off];
                    int keep = (lane & off) ? p16[k + off] : p16[k];
                    p16[k] = keep + __shfl_xor_sync(0xffffffffu, send, off);
                }
            }
        }
        // certified lower bound: d >= ||vhat-qhat|| - ||ev|| - ||eq|| - pad
        float t  = mynvh2 + cnqh2 - 2.f * ss * (float)p16[0];
        float lb = sqrtf(fmaxf(t, 0.f)) * (1.f - 1e-6f) - myenv - cenq - 0.01f;
        bool need = !(lb >= mind);                 // NaN/inf-safe

        // ---- queue flagged points (warp-aggregated append) ----
        unsigned wm = __ballot_sync(0xffffffffu, need);
        if (wm) {
            int base;
            if (lane == 0) base = atomicAdd(&s_cnt, __popc(wm));
            base = __shfl_sync(0xffffffffu, base, 0);
            if (need) {
                int off = __popc(wm & ((1u << lane) - 1u));
                s_qpt[base + off] = (short)myloc;
            }
        }
        __syncthreads();                                   // queue visible

        // ---- block-cooperative exact rechecks (bit-exact XLA reduce) ----
        const int cnt = s_cnt;
        for (int e = wid; e < cnt; e += NWARP) {
            const int p = s_qpt[e];
            const float* row = g_feat + (blockbase + p) * C_DIM;
            float a = 0.f;
            #pragma unroll
            for (int j = 0; j < 8; ++j) {
                float v = row[j * 32 + lane];
                float d = __fsub_rn(v, qv[j]);
                a = __fadd_rn(a, __fmul_rn(d, d));     // no contraction
            }
            #pragma unroll
            for (int off = 16; off; off >>= 1)
                a = __fadd_rn(a, __shfl_down_sync(0xffffffffu, a, off));
            if (lane == 0) s_res[p] = __fsqrt_rn(a);
        }
        __syncthreads();                                   // results visible

        if (need) mind = fminf(mind, s_res[myloc]);

        // ---- argmax key: [tag:15][mind:32][~idx:17]; tag = (it>>1)+1 ----
        const unsigned long long tag = (unsigned long long)((it >> 1) + 1);
        unsigned long long best = (tag << 49)
            | ((unsigned long long)__float_as_uint(mind) << 17)
            | ((unsigned)~mypoint & IDXMASK);
        #pragma unroll
        for (int off = 16; off; off >>= 1) {
            unsigned long long o = __shfl_xor_sync(0xffffffffu, best, off);
            if (o > best) best = o;
        }
        if (lane == 0) swarp[wid] = best;
        __syncthreads();                                   // sync A

        // ---- barrier: atomicMax key + counter + spin (proven mechanism) ----
        if (wid == 0) {
            unsigned long long b = (lane < NWARP) ? swarp[lane] : 0ULL;
            #pragma unroll
            for (int off = 16; off; off >>= 1) {
                unsigned long long o = __shfl_xor_sync(0xffffffffu, b, off);
                if (o > b) b = o;
            }
            if (lane == 0) {
                atomicMax(&g_key[it & 1], b);
                __threadfence();                           // order max before add
                atomicAdd((unsigned*)&g_bar, 1u);
                const unsigned target = (unsigned)NBLK * (unsigned)(it + 1);
                while (g_bar < target) { }                 // grid barrier spin
                __threadfence();                           // acquire
                unsigned long long g =
                    *(volatile unsigned long long*)&g_key[it & 1];
                const int q = (int)(IDXMASK - (unsigned)(g & IDXMASK));
                s_qidx = q;
                if (blockIdx.x == 0) g_sel[it + 1] = q;
            }
        }
        if (tid == 32) s_cnt = 0;                          // reset for next iter
        __syncthreads();                                   // sync B

        // ---- next-query loads straight into registers ----
        const int q = s_qidx;
        qrow = g_q8[(size_t)q * 32 + lane];
        qm   = g_qmeta[q];
        const float* qr = g_feat + (size_t)q * C_DIM;
        #pragma unroll
        for (int j = 0; j < 8; ++j) qv[j] = qr[j * 32 + lane];
    }
}

// ---------------------------------------------------------------------------
// Gather: out = [sampled feats (491*256) | sampled weights (491) | indices (491)]
// ---------------------------------------------------------------------------
__global__ void k_gather(const float* __restrict__ w, float* __restrict__ out) {
    const int s = blockIdx.x;           // 0..490
    const int idx = g_sel[s];
    out[s * C_DIM + threadIdx.x] = g_feat[(size_t)idx * C_DIM + threadIdx.x];
    if (threadIdx.x == 0) {
        out[NSAMP * C_DIM + s]         = w[idx];
        out[NSAMP * C_DIM + NSAMP + s] = (float)idx;
    }
}

// ---------------------------------------------------------------------------
extern "C" void kernel_launch(void* const* d_in, const int* in_sizes, int n_in,
                              void* d_out, int out_size) {
    const float* features = (const float*)d_in[0];   // [96,256,32,32] f32
    const float* weights  = (const float*)d_in[1];   // [98304] f32
    (void)in_sizes; (void)n_in; (void)out_size;      // num_samples fixed at 491

    const size_t dyn_smem = (size_t)TILE_U2 * sizeof(uint2);   // 192 KB
    static bool attr_set = false;
    if (!attr_set) {
        cudaFuncSetAttribute(k_fps, cudaFuncAttributeMaxDynamicSharedMemorySize,
                             (int)dyn_smem);
        attr_set = true;
    }

    k_init<<<(96 * 256), 256>>>(features);
    k_quant<<<N_PTS / 8, 256>>>();
    k_fps<<<NBLK, NTHR, dyn_smem>>>();
    k_gather<<<NSAMP, C_DIM>>>(weights, (float*)d_out);
}